// round 2
// baseline (speedup 1.0000x reference)
#include <cuda_runtime.h>
#include <float.h>
#include <math.h>

#define BATCH   1024
#define DIM     384
#define NCUBES  131072
#define TOPK    16

#define BT      128           // queries per CTA tile
#define CT      128           // cubes per n-tile
#define KT      32            // k tile
#define NCHUNK  1024          // cubes per CTA (chunk)
#define NTILES  (NCHUNK/CT)     // 8
#define NCHUNKS (NCUBES/NCHUNK) // 128
#define BTILES  (BATCH/BT)      // 8
#define LVP     17            // padded topk list stride

// dynamic smem layout (bytes)
#define OFF_Q2   0                       // float2 [KT][BT]  = 32768
#define OFF_ES   (OFF_Q2 + KT*BT*8)      // float  [KT][CT]  = 16384
#define OFF_DS   (OFF_ES + KT*CT*4)      // float  [KT][CT]  = 16384
#define SC_PITCH (BT + 4)                // 132 floats per cube row
#define SZ_UNION (CT * SC_PITCH * 4)     // 67584 (> 65536 tiles)
#define OFF_LV   SZ_UNION                // float [BT][LVP] = 8704
#define OFF_LI   (OFF_LV + BT*LVP*4)     // int   [BT][LVP] = 8704
#define SMEM_SZ  (OFF_LI + BT*LVP*4)     // 84992

typedef unsigned long long u64;

// ---------------- device scratch ----------------
__device__ float g_qn[BATCH * DIM];
__device__ float g_cand_v[BATCH * NCHUNKS * TOPK];
__device__ int   g_cand_i[BATCH * NCHUNKS * TOPK];

__device__ __forceinline__ void fma2(u64 &acc, u64 a, u64 b) {
    asm("fma.rn.f32x2 %0, %1, %2, %0;" : "+l"(acc) : "l"(a), "l"(b));
}
__device__ __forceinline__ float2 up2(u64 u) {
    float2 f;
    asm("mov.b64 {%0, %1}, %2;" : "=f"(f.x), "=f"(f.y) : "l"(u));
    return f;
}

// ---------------- kernel 1: normalize queries ----------------
__global__ __launch_bounds__(128) void norm_q_kernel(const float* __restrict__ q) {
    int b = blockIdx.x;
    const float* row = q + b * DIM;
    float s = 0.f;
    for (int i = threadIdx.x; i < DIM; i += 128) { float v = row[i]; s += v * v; }
    __shared__ float red[4];
    #pragma unroll
    for (int o = 16; o; o >>= 1) s += __shfl_xor_sync(0xffffffffu, s, o);
    if ((threadIdx.x & 31) == 0) red[threadIdx.x >> 5] = s;
    __syncthreads();
    if (threadIdx.x == 0) {
        float t = red[0] + red[1] + red[2] + red[3];
        red[0] = 1.0f / fmaxf(sqrtf(t), 1e-12f);
    }
    __syncthreads();
    float sc = red[0];
    for (int i = threadIdx.x; i < DIM; i += 128) g_qn[b * DIM + i] = row[i] * sc;
}

// ---------------- kernel 2: packed-f32x2 scores + fused per-chunk top-16 ----------------
// grid = (BTILES, NCHUNKS), block = 256, dynamic smem = SMEM_SZ
__global__ __launch_bounds__(256) void score_kernel(const float* __restrict__ emb,
                                                    const float* __restrict__ dual) {
    extern __shared__ char smraw[];
    float2 (*Q2)[BT]      = (float2(*)[BT])(smraw + OFF_Q2);   // (q,q) duplicated
    float  (*Es)[CT]      = (float (*)[CT])(smraw + OFF_ES);
    float  (*Ds)[CT]      = (float (*)[CT])(smraw + OFF_DS);
    float  (*sc)[SC_PITCH]= (float (*)[SC_PITCH])smraw;        // union with tiles
    float  (*lv)[LVP]     = (float (*)[LVP])(smraw + OFF_LV);
    int    (*li)[LVP]     = (int   (*)[LVP])(smraw + OFF_LI);

    const int btile = blockIdx.x;
    const int chunk = blockIdx.y;
    const int qbase = btile * BT;
    const int nbase = chunk * NCHUNK;
    const int tid   = threadIdx.x;
    const int tq    = tid >> 4;     // 0..15
    const int tc    = tid & 15;     // 0..15
    const int q0    = tq * 8;
    const int c0    = tc * 8;

    if (tid < BT) {
        #pragma unroll
        for (int k = 0; k < TOPK; k++) { lv[tid][k] = -FLT_MAX; li[tid][k] = 0; }
    }

    for (int nt = 0; nt < NTILES; nt++) {
        const int cbase = nbase + nt * CT;
        u64 accE[8][4], accD[8][4];
        #pragma unroll
        for (int i = 0; i < 8; i++)
            #pragma unroll
            for (int j = 0; j < 4; j++) { accE[i][j] = 0ull; accD[i][j] = 0ull; }

        for (int kt = 0; kt < DIM; kt += KT) {
            __syncthreads();   // previous consumers done (compute / topk scan)
            // Q tile: 128 rows x 8 float4, stored k-major DUPLICATED (q,q)
            for (int l = tid; l < BT * 8; l += 256) {
                int r = l >> 3, c4 = l & 7;
                float4 v = *(const float4*)&g_qn[(qbase + r) * DIM + kt + c4 * 4];
                Q2[c4 * 4 + 0][r] = make_float2(v.x, v.x);
                Q2[c4 * 4 + 1][r] = make_float2(v.y, v.y);
                Q2[c4 * 4 + 2][r] = make_float2(v.z, v.z);
                Q2[c4 * 4 + 3][r] = make_float2(v.w, v.w);
            }
            // E + D tiles: 128 rows x 8 float4 each, k-major
            for (int l = tid; l < CT * 8; l += 256) {
                int r = l >> 3, c4 = l & 7;
                int goff = (cbase + r) * DIM + kt + c4 * 4;
                float4 v = *(const float4*)&emb[goff];
                Es[c4 * 4 + 0][r] = v.x;
                Es[c4 * 4 + 1][r] = v.y;
                Es[c4 * 4 + 2][r] = v.z;
                Es[c4 * 4 + 3][r] = v.w;
                float4 w = *(const float4*)&dual[goff];
                Ds[c4 * 4 + 0][r] = w.x;
                Ds[c4 * 4 + 1][r] = w.y;
                Ds[c4 * 4 + 2][r] = w.z;
                Ds[c4 * 4 + 3][r] = w.w;
            }
            __syncthreads();

            #pragma unroll 4
            for (int kk = 0; kk < KT; kk++) {
                ulonglong2 qA = *(const ulonglong2*)&Q2[kk][q0];
                ulonglong2 qB = *(const ulonglong2*)&Q2[kk][q0 + 2];
                ulonglong2 qC = *(const ulonglong2*)&Q2[kk][q0 + 4];
                ulonglong2 qD = *(const ulonglong2*)&Q2[kk][q0 + 6];
                ulonglong2 eA = *(const ulonglong2*)&Es[kk][c0];
                ulonglong2 eB = *(const ulonglong2*)&Es[kk][c0 + 4];
                ulonglong2 dA = *(const ulonglong2*)&Ds[kk][c0];
                ulonglong2 dB = *(const ulonglong2*)&Ds[kk][c0 + 4];
                u64 qd[8] = {qA.x, qA.y, qB.x, qB.y, qC.x, qC.y, qD.x, qD.y};
                u64 ep[4] = {eA.x, eA.y, eB.x, eB.y};
                u64 dp[4] = {dA.x, dA.y, dB.x, dB.y};
                #pragma unroll
                for (int i = 0; i < 8; i++) {
                    #pragma unroll
                    for (int j = 0; j < 4; j++) {
                        fma2(accE[i][j], qd[i], ep[j]);
                        fma2(accD[i][j], qd[i], dp[j]);
                    }
                }
            }
        }

        __syncthreads();   // compute reads of tiles done; write scores into union
        #pragma unroll
        for (int i = 0; i < 8; i++) {
            #pragma unroll
            for (int j = 0; j < 4; j++) {
                float2 se = up2(accE[i][j]);
                float2 sd = up2(accD[i][j]);
                sc[c0 + 2 * j + 0][q0 + i] = se.x + 0.35f * fmaxf(sd.x, 0.f);
                sc[c0 + 2 * j + 1][q0 + i] = se.y + 0.35f * fmaxf(sd.y, 0.f);
            }
        }
        __syncthreads();

        // per-query top-16 update (one thread per query)
        if (tid < BT) {
            float* mylv = lv[tid];
            int*   myli = li[tid];
            float  thr  = mylv[0];
            for (int c = 0; c < CT; c++) {
                float s = sc[c][tid];
                if (s > thr) {
                    int j = 0;
                    while (j < TOPK - 1 && mylv[j + 1] < s) {
                        mylv[j] = mylv[j + 1];
                        myli[j] = myli[j + 1];
                        j++;
                    }
                    mylv[j] = s;
                    myli[j] = cbase + c;
                    thr = mylv[0];
                }
            }
        }
        // next nt's first __syncthreads separates scan from tile loads
    }

    __syncthreads();
    if (tid < BT) {
        int q = qbase + tid;
        int base = (q * NCHUNKS + chunk) * TOPK;
        #pragma unroll
        for (int k = 0; k < TOPK; k++) {
            g_cand_v[base + k] = lv[tid][TOPK - 1 - k];
            g_cand_i[base + k] = li[tid][TOPK - 1 - k];
        }
    }
}

// ---------------- kernel 3: merge 128*16 candidates -> global top-16 ----------------
__global__ __launch_bounds__(256) void merge_kernel(float* __restrict__ out, int out_size) {
    const int q = blockIdx.x;
    const int tid = threadIdx.x;
    const int NC = NCHUNKS * TOPK;   // 2048
    __shared__ float v[NCHUNKS * TOPK];
    __shared__ int   id[NCHUNKS * TOPK];
    __shared__ float bwv[8];
    __shared__ int   bwi[8];
    __shared__ int   bws[8];

    for (int l = tid; l < NC; l += 256) {
        v[l]  = g_cand_v[q * NC + l];
        id[l] = g_cand_i[q * NC + l];
    }
    __syncthreads();

    for (int k = 0; k < TOPK; k++) {
        float bv = -FLT_MAX;
        int   bi = 0x7fffffff;
        int   bs = 0;
        for (int l = tid; l < NC; l += 256) {
            float vv = v[l];
            int   ii = id[l];
            if (vv > bv || (vv == bv && ii < bi)) { bv = vv; bi = ii; bs = l; }
        }
        #pragma unroll
        for (int o = 16; o; o >>= 1) {
            float ov = __shfl_xor_sync(0xffffffffu, bv, o);
            int   oi = __shfl_xor_sync(0xffffffffu, bi, o);
            int   os = __shfl_xor_sync(0xffffffffu, bs, o);
            if (ov > bv || (ov == bv && oi < bi)) { bv = ov; bi = oi; bs = os; }
        }
        if ((tid & 31) == 0) { bwv[tid >> 5] = bv; bwi[tid >> 5] = bi; bws[tid >> 5] = bs; }
        __syncthreads();
        if (tid == 0) {
            float fv = bwv[0]; int fi = bwi[0]; int fs = bws[0];
            #pragma unroll
            for (int w = 1; w < 8; w++) {
                if (bwv[w] > fv || (bwv[w] == fv && bwi[w] < fi)) {
                    fv = bwv[w]; fi = bwi[w]; fs = bws[w];
                }
            }
            out[q * TOPK + k] = fv;
            if (out_size >= 2 * BATCH * TOPK)
                out[BATCH * TOPK + q * TOPK + k] = (float)fi;
            v[fs] = -FLT_MAX;
        }
        __syncthreads();
    }
}

// ---------------- launch ----------------
extern "C" void kernel_launch(void* const* d_in, const int* in_sizes, int n_in,
                              void* d_out, int out_size) {
    const float* query = (const float*)d_in[0];
    const float* emb   = (const float*)d_in[1];
    const float* dual  = (const float*)d_in[2];
    float* out = (float*)d_out;

    cudaFuncSetAttribute(score_kernel,
                         cudaFuncAttributeMaxDynamicSharedMemorySize, SMEM_SZ);

    norm_q_kernel<<<BATCH, 128>>>(query);

    dim3 grid(BTILES, NCHUNKS);
    score_kernel<<<grid, 256, SMEM_SZ>>>(emb, dual);

    merge_kernel<<<BATCH, 256>>>(out, out_size);
}

// round 4
// speedup vs baseline: 2.3618x; 2.3618x over previous
#include <cuda_runtime.h>
#include <cuda_fp16.h>
#include <float.h>
#include <math.h>
#include <stdint.h>

#define BATCH   1024
#define DIM     384
#define NCUBES  131072
#define TOPK    16

#define BT      64              // queries per CTA
#define CT      128             // cubes per n-tile
#define KT      32              // k chunk
#define NCHUNK  2048            // cubes per CTA chunk
#define NTILES  (NCHUNK/CT)     // 16
#define NCHUNKS (NCUBES/NCHUNK) // 64
#define BTILES  (BATCH/BT)      // 16
#define LVP     17

#define QPITCH  40              // smem row pitch in halfs (32 + 8 pad)

// ---- dynamic smem layout (bytes) ----
#define OFF_QH   0
#define OFF_QL   (OFF_QH + BT*QPITCH*2)     // 5120
#define OFF_EH   (OFF_QL + BT*QPITCH*2)     // 10240
#define OFF_EL   (OFF_EH + CT*QPITCH*2)     // 20480
#define OFF_DH   (OFF_EL + CT*QPITCH*2)     // 30720
#define OFF_DL   (OFF_DH + CT*QPITCH*2)     // 40960
#define SZ_TILES (OFF_DL + CT*QPITCH*2)     // 51200
#define SC_PITCH (BT + 4)                   // 68 floats
#define OFF_LV   SZ_TILES
#define OFF_LI   (OFF_LV + BT*LVP*4)
#define SMEM_SZ  (OFF_LI + BT*LVP*4)        // 59904

// ---------------- device scratch ----------------
__device__ __half g_Qh[BATCH * DIM];
__device__ __half g_Ql[BATCH * DIM];
__device__ __half g_Eh[NCUBES * DIM];
__device__ __half g_El[NCUBES * DIM];
__device__ __half g_Dh[NCUBES * DIM];
__device__ __half g_Dl[NCUBES * DIM];
__device__ float  g_cand_v[BATCH * NCHUNKS * TOPK];
__device__ int    g_cand_i[BATCH * NCHUNKS * TOPK];

// ---------------- PTX helpers ----------------
__device__ __forceinline__ void ldsm4(uint32_t* r, uint32_t addr) {
    asm volatile("ldmatrix.sync.aligned.m8n8.x4.shared.b16 {%0,%1,%2,%3}, [%4];"
                 : "=r"(r[0]), "=r"(r[1]), "=r"(r[2]), "=r"(r[3]) : "r"(addr));
}
__device__ __forceinline__ void mma16816(float* d, const uint32_t* a, const uint32_t* b) {
    asm volatile("mma.sync.aligned.m16n8k16.row.col.f32.f16.f16.f32 "
                 "{%0,%1,%2,%3}, {%4,%5,%6,%7}, {%8,%9}, {%0,%1,%2,%3};"
                 : "+f"(d[0]), "+f"(d[1]), "+f"(d[2]), "+f"(d[3])
                 : "r"(a[0]), "r"(a[1]), "r"(a[2]), "r"(a[3]),
                   "r"(b[0]), "r"(b[1]));
}

// ---------------- kernel 1: normalize + split queries ----------------
__global__ __launch_bounds__(128) void norm_split_q_kernel(const float* __restrict__ q) {
    int b = blockIdx.x;
    const float* row = q + b * DIM;
    float s = 0.f;
    for (int i = threadIdx.x; i < DIM; i += 128) { float v = row[i]; s += v * v; }
    __shared__ float red[4];
    #pragma unroll
    for (int o = 16; o; o >>= 1) s += __shfl_xor_sync(0xffffffffu, s, o);
    if ((threadIdx.x & 31) == 0) red[threadIdx.x >> 5] = s;
    __syncthreads();
    if (threadIdx.x == 0) {
        float t = red[0] + red[1] + red[2] + red[3];
        red[0] = 1.0f / fmaxf(sqrtf(t), 1e-12f);
    }
    __syncthreads();
    float sc = red[0];
    for (int i = threadIdx.x; i < DIM; i += 128) {
        float v = row[i] * sc;
        __half h = __float2half_rn(v);
        g_Qh[b * DIM + i] = h;
        g_Ql[b * DIM + i] = __float2half_rn(v - __half2float(h));
    }
}

// ---------------- kernel 1b: split E and D into fp16 hi/lo ----------------
__global__ __launch_bounds__(256) void split_ed_kernel(const float* __restrict__ emb,
                                                       const float* __restrict__ dual) {
    const int total4 = NCUBES * DIM / 4;
    for (int i = blockIdx.x * blockDim.x + threadIdx.x; i < total4;
         i += gridDim.x * blockDim.x) {
        float4 v = ((const float4*)emb)[i];
        __half hx = __float2half_rn(v.x), hy = __float2half_rn(v.y);
        __half hz = __float2half_rn(v.z), hw = __float2half_rn(v.w);
        uint2 hi, lo;
        ((__half2*)&hi)[0] = __halves2half2(hx, hy);
        ((__half2*)&hi)[1] = __halves2half2(hz, hw);
        ((__half2*)&lo)[0] = __halves2half2(__float2half_rn(v.x - __half2float(hx)),
                                            __float2half_rn(v.y - __half2float(hy)));
        ((__half2*)&lo)[1] = __halves2half2(__float2half_rn(v.z - __half2float(hz)),
                                            __float2half_rn(v.w - __half2float(hw)));
        ((uint2*)g_Eh)[i] = hi;
        ((uint2*)g_El)[i] = lo;

        float4 w = ((const float4*)dual)[i];
        hx = __float2half_rn(w.x); hy = __float2half_rn(w.y);
        hz = __float2half_rn(w.z); hw = __float2half_rn(w.w);
        ((__half2*)&hi)[0] = __halves2half2(hx, hy);
        ((__half2*)&hi)[1] = __halves2half2(hz, hw);
        ((__half2*)&lo)[0] = __halves2half2(__float2half_rn(w.x - __half2float(hx)),
                                            __float2half_rn(w.y - __half2float(hy)));
        ((__half2*)&lo)[1] = __halves2half2(__float2half_rn(w.z - __half2float(hz)),
                                            __float2half_rn(w.w - __half2float(hw)));
        ((uint2*)g_Dh)[i] = hi;
        ((uint2*)g_Dl)[i] = lo;
    }
}

// ---------------- kernel 2: HMMA split-GEMM + fused per-chunk top-16 ----------------
// grid = (BTILES, NCHUNKS), block = 256 (8 warps, 2x4), dynamic smem
__global__ __launch_bounds__(256, 2) void score_kernel() {
    extern __shared__ char sm[];
    __half* Qh_s = (__half*)(sm + OFF_QH);
    __half* Ql_s = (__half*)(sm + OFF_QL);
    __half* Eh_s = (__half*)(sm + OFF_EH);
    __half* El_s = (__half*)(sm + OFF_EL);
    __half* Dh_s = (__half*)(sm + OFF_DH);
    __half* Dl_s = (__half*)(sm + OFF_DL);
    float (*scb)[SC_PITCH] = (float(*)[SC_PITCH])sm;          // union with tiles
    float (*lv)[LVP] = (float(*)[LVP])(sm + OFF_LV);
    int   (*li)[LVP] = (int  (*)[LVP])(sm + OFF_LI);

    const int tid    = threadIdx.x;
    const int lane   = tid & 31;
    const int warp   = tid >> 5;
    const int warp_q = warp >> 2;          // 0..1 -> q offset *32
    const int warp_c = warp & 3;           // 0..3 -> c offset *32
    const int qbase  = blockIdx.x * BT;
    const int nbase  = blockIdx.y * NCHUNK;

    const uint32_t sQh = (uint32_t)__cvta_generic_to_shared(Qh_s);
    const uint32_t sQl = (uint32_t)__cvta_generic_to_shared(Ql_s);
    const uint32_t sEh = (uint32_t)__cvta_generic_to_shared(Eh_s);
    const uint32_t sEl = (uint32_t)__cvta_generic_to_shared(El_s);
    const uint32_t sDh = (uint32_t)__cvta_generic_to_shared(Dh_s);
    const uint32_t sDl = (uint32_t)__cvta_generic_to_shared(Dl_s);

    // ldmatrix lane addressing offsets (in halfs)
    const int aRow = (lane & 15);               // + mi*16 + warp_q*32
    const int aCol = (lane >> 4) * 8;           // + ks
    const int bRow = (lane & 7) + ((lane >> 4) & 1) * 8;  // + j*16 + warp_c*32
    const int bCol = ((lane >> 3) & 1) * 8;     // + ks

    if (tid < BT) {
        #pragma unroll
        for (int k = 0; k < TOPK; k++) { lv[tid][k] = -FLT_MAX; li[tid][k] = 0; }
    }

    for (int nt = 0; nt < NTILES; nt++) {
        const int cbase = nbase + nt * CT;
        float accE[2][4][4], accD[2][4][4];
        #pragma unroll
        for (int mi = 0; mi < 2; mi++)
            #pragma unroll
            for (int ni = 0; ni < 4; ni++)
                #pragma unroll
                for (int r = 0; r < 4; r++) { accE[mi][ni][r] = 0.f; accD[mi][ni][r] = 0.f; }

        for (int kt = 0; kt < DIM; kt += KT) {
            __syncthreads();   // previous consumers of smem done
            {   // Q tiles: 64 rows x 4 chunks of 8 halfs (16B)
                int r = tid >> 2, ch = (tid & 3) * 8;
                int g = (qbase + r) * DIM + kt + ch;
                *(uint4*)&Qh_s[r * QPITCH + ch] = *(const uint4*)&g_Qh[g];
                *(uint4*)&Ql_s[r * QPITCH + ch] = *(const uint4*)&g_Ql[g];
            }
            #pragma unroll
            for (int l = 0; l < 2; l++) {   // E/D tiles: 128 rows x 4 chunks
                int idx = tid + l * 256;
                int r = idx >> 2, ch = (idx & 3) * 8;
                int g = (cbase + r) * DIM + kt + ch;
                *(uint4*)&Eh_s[r * QPITCH + ch] = *(const uint4*)&g_Eh[g];
                *(uint4*)&El_s[r * QPITCH + ch] = *(const uint4*)&g_El[g];
                *(uint4*)&Dh_s[r * QPITCH + ch] = *(const uint4*)&g_Dh[g];
                *(uint4*)&Dl_s[r * QPITCH + ch] = *(const uint4*)&g_Dl[g];
            }
            __syncthreads();

            #pragma unroll
            for (int ks = 0; ks < KT; ks += 16) {
                uint32_t aH[2][4], aL[2][4];
                #pragma unroll
                for (int mi = 0; mi < 2; mi++) {
                    uint32_t off = ((warp_q * 32 + mi * 16 + aRow) * QPITCH + ks + aCol) * 2;
                    ldsm4(aH[mi], sQh + off);
                    ldsm4(aL[mi], sQl + off);
                }
                #pragma unroll
                for (int j = 0; j < 2; j++) {   // two 16-wide n groups
                    uint32_t off = ((warp_c * 32 + j * 16 + bRow) * QPITCH + ks + bCol) * 2;
                    uint32_t bEh[4], bEl[4], bDh[4], bDl[4];
                    ldsm4(bEh, sEh + off);
                    ldsm4(bEl, sEl + off);
                    ldsm4(bDh, sDh + off);
                    ldsm4(bDl, sDl + off);
                    #pragma unroll
                    for (int mi = 0; mi < 2; mi++) {
                        #pragma unroll
                        for (int p = 0; p < 2; p++) {
                            int ni = j * 2 + p;
                            mma16816(accE[mi][ni], aH[mi], &bEh[2 * p]);
                            mma16816(accE[mi][ni], aH[mi], &bEl[2 * p]);
                            mma16816(accE[mi][ni], aL[mi], &bEh[2 * p]);
                            mma16816(accD[mi][ni], aH[mi], &bDh[2 * p]);
                            mma16816(accD[mi][ni], aH[mi], &bDl[2 * p]);
                            mma16816(accD[mi][ni], aL[mi], &bDh[2 * p]);
                        }
                    }
                }
            }
        }

        __syncthreads();   // tile reads done; write scores into union
        {
            int m_off = lane >> 2, n_off = (lane & 3) * 2;
            #pragma unroll
            for (int mi = 0; mi < 2; mi++) {
                #pragma unroll
                for (int ni = 0; ni < 4; ni++) {
                    int m = warp_q * 32 + mi * 16 + m_off;
                    int n = warp_c * 32 + ni * 8 + n_off;
                    scb[n    ][m    ] = accE[mi][ni][0] + 0.35f * fmaxf(accD[mi][ni][0], 0.f);
                    scb[n + 1][m    ] = accE[mi][ni][1] + 0.35f * fmaxf(accD[mi][ni][1], 0.f);
                    scb[n    ][m + 8] = accE[mi][ni][2] + 0.35f * fmaxf(accD[mi][ni][2], 0.f);
                    scb[n + 1][m + 8] = accE[mi][ni][3] + 0.35f * fmaxf(accD[mi][ni][3], 0.f);
                }
            }
        }
        __syncthreads();

        // per-query top-16 update (one thread per query)
        if (tid < BT) {
            float* mylv = lv[tid];
            int*   myli = li[tid];
            float  thr  = mylv[0];
            for (int c = 0; c < CT; c++) {
                float s = scb[c][tid];
                if (s > thr) {
                    int j = 0;
                    while (j < TOPK - 1 && mylv[j + 1] < s) {
                        mylv[j] = mylv[j + 1];
                        myli[j] = myli[j + 1];
                        j++;
                    }
                    mylv[j] = s;
                    myli[j] = cbase + c;
                    thr = mylv[0];
                }
            }
        }
        // next iteration's first __syncthreads separates scan from tile loads
    }

    __syncthreads();
    if (tid < BT) {
        int q = qbase + tid;
        int base = (q * NCHUNKS + blockIdx.y) * TOPK;
        #pragma unroll
        for (int k = 0; k < TOPK; k++) {
            g_cand_v[base + k] = lv[tid][TOPK - 1 - k];
            g_cand_i[base + k] = li[tid][TOPK - 1 - k];
        }
    }
}

// ---------------- kernel 3: merge 64*16 candidates -> global top-16 ----------------
__global__ __launch_bounds__(256) void merge_kernel(float* __restrict__ out, int out_size) {
    const int q = blockIdx.x;
    const int tid = threadIdx.x;
    const int NC = NCHUNKS * TOPK;   // 1024
    __shared__ float v[NCHUNKS * TOPK];
    __shared__ int   id[NCHUNKS * TOPK];
    __shared__ float bwv[8];
    __shared__ int   bwi[8];
    __shared__ int   bws[8];

    for (int l = tid; l < NC; l += 256) {
        v[l]  = g_cand_v[q * NC + l];
        id[l] = g_cand_i[q * NC + l];
    }
    __syncthreads();

    for (int k = 0; k < TOPK; k++) {
        float bv = -FLT_MAX;
        int   bi = 0x7fffffff;
        int   bs = 0;
        for (int l = tid; l < NC; l += 256) {
            float vv = v[l];
            int   ii = id[l];
            if (vv > bv || (vv == bv && ii < bi)) { bv = vv; bi = ii; bs = l; }
        }
        #pragma unroll
        for (int o = 16; o; o >>= 1) {
            float ov = __shfl_xor_sync(0xffffffffu, bv, o);
            int   oi = __shfl_xor_sync(0xffffffffu, bi, o);
            int   os = __shfl_xor_sync(0xffffffffu, bs, o);
            if (ov > bv || (ov == bv && oi < bi)) { bv = ov; bi = oi; bs = os; }
        }
        if ((tid & 31) == 0) { bwv[tid >> 5] = bv; bwi[tid >> 5] = bi; bws[tid >> 5] = bs; }
        __syncthreads();
        if (tid == 0) {
            float fv = bwv[0]; int fi = bwi[0]; int fs = bws[0];
            #pragma unroll
            for (int w = 1; w < 8; w++) {
                if (bwv[w] > fv || (bwv[w] == fv && bwi[w] < fi)) {
                    fv = bwv[w]; fi = bwi[w]; fs = bws[w];
                }
            }
            out[q * TOPK + k] = fv;
            if (out_size >= 2 * BATCH * TOPK)
                out[BATCH * TOPK + q * TOPK + k] = (float)fi;
            v[fs] = -FLT_MAX;
        }
        __syncthreads();
    }
}

// ---------------- launch ----------------
extern "C" void kernel_launch(void* const* d_in, const int* in_sizes, int n_in,
                              void* d_out, int out_size) {
    const float* query = (const float*)d_in[0];
    const float* emb   = (const float*)d_in[1];
    const float* dual  = (const float*)d_in[2];
    float* out = (float*)d_out;

    cudaFuncSetAttribute(score_kernel,
                         cudaFuncAttributeMaxDynamicSharedMemorySize, SMEM_SZ);

    norm_split_q_kernel<<<BATCH, 128>>>(query);
    split_ed_kernel<<<8192, 256>>>(emb, dual);

    dim3 grid(BTILES, NCHUNKS);
    score_kernel<<<grid, 256, SMEM_SZ>>>();

    merge_kernel<<<BATCH, 256>>>(out, out_size);
}